// round 17
// baseline (speedup 1.0000x reference)
#include <cuda_runtime.h>
#include <cuda_bf16.h>
#include <cstdint>

// Problem dims
#define TT 2048
#define BB 64
#define FFD 256
#define HH 256
#define NG 768  // 3*H

// Recurrence config: 32 clusters x 4 CTAs, 256 threads
#define CSZ 4
#define NCTA 128
#define NT 256

// -------- device scratch --------
__device__ float g_xi[(size_t)TT * BB * NG];     // 2048*64*768
__device__ float g_dump[(size_t)TT * BB * HH];   // fallback ys sink

// -------- packed f32x2 helpers --------
__device__ __forceinline__ void ffma2(unsigned long long& d, unsigned long long a, unsigned long long b) {
    asm volatile("fma.rn.f32x2 %0, %1, %2, %0;" : "+l"(d) : "l"(a), "l"(b));
}
__device__ __forceinline__ unsigned long long dup2(float a) {
    unsigned long long d;
    asm("mov.b64 %0, {%1, %1};" : "=l"(d) : "f"(a));
    return d;
}
__device__ __forceinline__ unsigned long long pack2(float a, float b) {
    unsigned long long d;
    asm("mov.b64 %0, {%1, %2};" : "=l"(d) : "f"(a), "f"(b));
    return d;
}
__device__ __forceinline__ float2 unpack2(unsigned long long d) {
    float2 f;
    asm("mov.b64 {%0, %1}, %2;" : "=f"(f.x), "=f"(f.y) : "l"(d));
    return f;
}
__device__ __forceinline__ float tanh_ap(float x) {
    float y;
    asm("tanh.approx.f32 %0, %1;" : "=f"(y) : "f"(x));
    return y;
}
__device__ __forceinline__ float sigmoid_ap(float x) {
    return 0.5f * tanh_ap(0.5f * x) + 0.5f;
}
__device__ __forceinline__ uint32_t smem_u32(const void* p) {
    uint32_t a;
    asm("{ .reg .u64 t; cvta.to.shared.u64 t, %1; cvt.u32.u64 %0, t; }" : "=r"(a) : "l"(p));
    return a;
}
// CTA-scope wait: no cluster-scope acquire -> no CCTL.IVALL on the poll loop.
__device__ __forceinline__ void mbar_wait_cta(uint32_t mbar, unsigned parity) {
    asm volatile(
        "{\n\t.reg .pred p;\n\t"
        "WAIT_%=:\n\t"
        "mbarrier.try_wait.parity.acquire.cta.shared::cta.b64 p, [%0], %1, 0x989680;\n\t"
        "@!p bra WAIT_%=;\n\t}"
        :: "r"(mbar), "r"(parity) : "memory");
}
// Remote tx-tracked 8B store (dup'd f32 pair) to peer CTA smem.
__device__ __forceinline__ void st_async_u64(uint32_t daddr, unsigned long long v, uint32_t maddr) {
    asm volatile(
        "st.async.shared::cluster.mbarrier::complete_tx::bytes.b64 [%0], %1, [%2];"
        :: "r"(daddr), "l"(v), "r"(maddr) : "memory");
}

// ============================================================
// Kernel 1: xi = xs @ Wi (M=131072, K=256, N=768)
// Double-buffered smem ping-pong, register prefetch (R16-proven).
// ============================================================
__global__ __launch_bounds__(256, 2) void gemm_xi_kernel(const float* __restrict__ A,
                                                         const float* __restrict__ W) {
    __shared__ float As[2][16][132];
    __shared__ float Bs[2][16][128];
    const int tid = threadIdx.x;
    const int m0 = blockIdx.y * 128;
    const int n0 = blockIdx.x * 128;
    const int nt = tid & 15;
    const int mt = tid >> 4;

    const int af0 = tid;
    const int af1 = tid + 256;
    const int arow0 = af0 >> 2, akq0 = (af0 & 3) << 2;
    const int arow1 = af1 >> 2, akq1 = (af1 & 3) << 2;
    const int brow0 = af0 >> 5, bnq0 = (af0 & 31) << 2;
    const int brow1 = af1 >> 5, bnq1 = (af1 & 31) << 2;

    unsigned long long acc[8][4];
#pragma unroll
    for (int i = 0; i < 8; i++)
#pragma unroll
        for (int j = 0; j < 4; j++) acc[i][j] = 0ULL;

    float4 ra0 = *(const float4*)(A + (size_t)(m0 + arow0) * 256 + 0 + akq0);
    float4 ra1 = *(const float4*)(A + (size_t)(m0 + arow1) * 256 + 0 + akq1);
    float4 rb0 = *(const float4*)(W + (size_t)(0 + brow0) * 768 + n0 + bnq0);
    float4 rb1 = *(const float4*)(W + (size_t)(0 + brow1) * 768 + n0 + bnq1);

#pragma unroll 1
    for (int kti = 0; kti < 16; kti++) {
        const int p = kti & 1;
        As[p][akq0 + 0][arow0] = ra0.x; As[p][akq0 + 1][arow0] = ra0.y;
        As[p][akq0 + 2][arow0] = ra0.z; As[p][akq0 + 3][arow0] = ra0.w;
        As[p][akq1 + 0][arow1] = ra1.x; As[p][akq1 + 1][arow1] = ra1.y;
        As[p][akq1 + 2][arow1] = ra1.z; As[p][akq1 + 3][arow1] = ra1.w;
        *(float4*)&Bs[p][brow0][bnq0] = rb0;
        *(float4*)&Bs[p][brow1][bnq1] = rb1;
        __syncthreads();

        if (kti < 15) {
            const int kt = (kti + 1) * 16;
            ra0 = *(const float4*)(A + (size_t)(m0 + arow0) * 256 + kt + akq0);
            ra1 = *(const float4*)(A + (size_t)(m0 + arow1) * 256 + kt + akq1);
            rb0 = *(const float4*)(W + (size_t)(kt + brow0) * 768 + n0 + bnq0);
            rb1 = *(const float4*)(W + (size_t)(kt + brow1) * 768 + n0 + bnq1);
        }

#pragma unroll
        for (int k = 0; k < 16; k++) {
            float4 a0 = *(const float4*)&As[p][k][mt * 8];
            float4 a1 = *(const float4*)&As[p][k][mt * 8 + 4];
            ulonglong2 bA = *(const ulonglong2*)&Bs[p][k][nt * 8];
            ulonglong2 bB = *(const ulonglong2*)&Bs[p][k][nt * 8 + 4];
            float av[8] = {a0.x, a0.y, a0.z, a0.w, a1.x, a1.y, a1.z, a1.w};
#pragma unroll
            for (int i = 0; i < 8; i++) {
                unsigned long long ad = dup2(av[i]);
                ffma2(acc[i][0], ad, bA.x);
                ffma2(acc[i][1], ad, bA.y);
                ffma2(acc[i][2], ad, bB.x);
                ffma2(acc[i][3], ad, bB.y);
            }
        }
    }

#pragma unroll
    for (int i = 0; i < 8; i++) {
        float2 c0 = unpack2(acc[i][0]);
        float2 c1 = unpack2(acc[i][1]);
        float2 c2 = unpack2(acc[i][2]);
        float2 c3 = unpack2(acc[i][3]);
        size_t off = (size_t)(m0 + mt * 8 + i) * 768 + n0 + nt * 8;
        *(float4*)(g_xi + off)     = make_float4(c0.x, c0.y, c1.x, c1.y);
        *(float4*)(g_xi + off + 4) = make_float4(c2.x, c2.y, c3.x, c3.y);
    }
}

// ============================================================
// Kernel 2: clustered GRU recurrence — CSZ=4, BATCH-PIPELINED
// Two independent batch chains per cluster, half-step offset:
// b0's DSMEM transit hides under b1's compute and vice versa.
// Per-batch mbarriers mb[b][buf]; same expect_tx/acquire.cta protocol.
// ============================================================

// smem float offsets
#define OFF_RED 0        // [256 threads][8] partials (3 f32x2 + pad) -> 2048
#define OFF_HT  2048     // [2 buf][2 batch][256 k] dup'd ull = 1024 ull -> 2048 floats
#define OFF_MB  4096     // 4 mbarriers (u64 each) = 8 floats
#define SMEM_FLOATS 4104
#define SMEM_BYTES (SMEM_FLOATS * 4)

#define TX_B 2048u   // per batch per step: 4 ranks x 64 j x 8B

__global__ __launch_bounds__(NT, 1) __cluster_dims__(CSZ, 1, 1)
void gru_rec_kernel(const float* __restrict__ c,
                    const float* __restrict__ Wh,
                    const float* __restrict__ bh,
                    const float* __restrict__ b_in,
                    float* __restrict__ ys,
                    float* __restrict__ finalc) {
    extern __shared__ float sm[];
    float* sRED = sm + OFF_RED;
    float* sHT  = sm + OFF_HT;   // ull slot (buf,b,k) at ull idx (buf*2+b)*256 + k

    const int tid = threadIdx.x;
    uint32_t rank;
    asm("mov.u32 %0, %%cluster_ctarank;" : "=r"(rank));
    const int cid = blockIdx.x >> 2;          // cluster id 0..31 (batches 2cid, 2cid+1)

    const uint32_t mbase = smem_u32(sm + OFF_MB);   // mb[b][buf] at mbase + (b*2+buf)*8

    // ---- init mbarriers; arm [b][1] for step-0 sends ----
    if (tid == 0) {
#pragma unroll
        for (int i = 0; i < 4; i++)
            asm volatile("mbarrier.init.shared.b64 [%0], %1;" :: "r"(mbase + i * 8u), "r"(1u) : "memory");
        asm volatile("mbarrier.arrive.expect_tx.shared.b64 _, [%0], %1;"
                     :: "r"(mbase + 1u * 8u), "r"(TX_B) : "memory");   // mb[0][1]
        asm volatile("mbarrier.arrive.expect_tx.shared.b64 _, [%0], %1;"
                     :: "r"(mbase + 3u * 8u), "r"(TX_B) : "memory");   // mb[1][1]
    }

    // ---- phase-1 mapping + weight load into registers ----
    const int kc = tid >> 5;       // k-chunk 0..7 (32 k each)
    const int jp = tid & 31;       // j-pair 0..31 -> global j (rank*64 + 2jp, +1)
    const int j0w = (int)rank * 64 + jp * 2;

    unsigned long long wreg[96];   // [kk 0..31][g 0..2] f32x2 over j-pair
#pragma unroll
    for (int kk = 0; kk < 32; kk++) {
#pragma unroll
        for (int g = 0; g < 3; g++) {
            float2 w2 = __ldg((const float2*)(Wh + (size_t)(kc * 32 + kk) * 768 + g * 256 + j0w));
            wreg[kk * 3 + g] = pack2(w2.x, w2.y);
        }
    }

    // initial h (dup'd) into buf 0, both batches
    for (int idx = tid; idx < 512; idx += NT) {
        int b = idx >> 8;
        int k = idx & 255;
        float v = __ldg(c + (size_t)(cid * 2 + b) * 256 + k);
        *((unsigned long long*)sHT + (size_t)b * 256 + k) = dup2(v);
    }

    // gate mapping (tid < 128): b = tid>=64, jl = tid&63
    const int jl = tid & 63;
    const int bg = (tid >> 6) & 1;               // batch this gate thread owns
    const int j0 = (int)rank * 64 + jl;          // global j
    const int b_glob = cid * 2 + bg;
    const int jpr = jl >> 1;                     // producer j-pair
    const int half = jl & 1;                     // lane within pair

    float bhr = 0.f, bhz = 0.f, bhn = 0.f, bin = 0.f;
    if (tid < 128) {
        bhr = __ldg(bh + j0);
        bhz = __ldg(bh + 256 + j0);
        bhn = __ldg(bh + 512 + j0);
        bin = __ldg(b_in + j0);
    }

    // remote addresses for all 4 ranks (incl self)
    uint32_t ht_local = smem_u32(sHT);
    uint32_t rdata[CSZ], rmb[CSZ];
#pragma unroll
    for (int r = 0; r < CSZ; r++) {
        asm("mapa.shared::cluster.u32 %0, %1, %2;" : "=r"(rdata[r]) : "r"(ht_local), "r"(r));
        asm("mapa.shared::cluster.u32 %0, %1, %2;" : "=r"(rmb[r]) : "r"(mbase), "r"(r));
    }

    __syncthreads();
    // ONE-TIME: mbarriers + buf0 ready everywhere before any peer traffic
    asm volatile("barrier.cluster.arrive.aligned;" ::: "memory");
    asm volatile("barrier.cluster.wait.aligned;" ::: "memory");

    // prefetch xi for t=0 (each gate thread: its own batch)
    float xr = 0.f, xz = 0.f, xn = 0.f;
    if (tid < 128) {
        const float* xp = g_xi + (size_t)b_glob * 768 + j0;
        xr = __ldg(xp);
        xz = __ldg(xp + 256);
        xn = __ldg(xp + 512);
    }

    // parity trackers: ph[b][buf]
    unsigned ph00 = 0, ph01 = 0, ph10 = 0, ph11 = 0;

    for (int t = 0; t < TT; t++) {
        const int p = t & 1;
        const int n = p ^ 1;

#pragma unroll
        for (int bb = 0; bb < 2; bb++) {
            // -- mid-wait for b1's h (arrived during b0 half) --
            if (bb == 1 && t > 0) {
                uint32_t mb = mbase + (uint32_t)(2 + p) * 8u;   // mb[1][p]
                if (p) { mbar_wait_cta(mb, ph11); ph11 ^= 1; }
                else   { mbar_wait_cta(mb, ph10); ph10 ^= 1; }
            }

            // -- phase 1: GEMV partials for batch bb --
            unsigned long long a0 = 0ULL, a1 = 0ULL, a2 = 0ULL;
            {
                const unsigned long long* hb =
                    (const unsigned long long*)sHT + (size_t)(p * 2 + bb) * 256 + kc * 32;
#pragma unroll
                for (int k2 = 0; k2 < 16; k2++) {
                    ulonglong2 hh = *(const ulonglong2*)(hb + k2 * 2);  // k even, k odd
                    ffma2(a0, wreg[(k2 * 2) * 3 + 0], hh.x);
                    ffma2(a1, wreg[(k2 * 2) * 3 + 1], hh.x);
                    ffma2(a2, wreg[(k2 * 2) * 3 + 2], hh.x);
                    ffma2(a0, wreg[(k2 * 2 + 1) * 3 + 0], hh.y);
                    ffma2(a1, wreg[(k2 * 2 + 1) * 3 + 1], hh.y);
                    ffma2(a2, wreg[(k2 * 2 + 1) * 3 + 2], hh.y);
                }
            }
            {
                float* rp = sRED + tid * 8;
                ulonglong2 v;
                v.x = a0; v.y = a1;
                *(ulonglong2*)rp = v;
                *(unsigned long long*)(rp + 4) = a2;
            }
            __syncthreads();

            // rearm mb[bb][p] for sends at step t+1 (just consumed this step)
            if (tid == 128 && t + 2 < TT) {
                uint32_t mb = mbase + (uint32_t)(bb * 2 + p) * 8u;
                asm volatile("mbarrier.arrive.expect_tx.shared.b64 _, [%0], %1;"
                             :: "r"(mb), "r"(TX_B) : "memory");
            }

            // -- gates for batch bb (its 64 owner threads) --
            if (tid < 128 && bg == bb) {
                float hr = 0.f, hz = 0.f, hn = 0.f;
                const float* rp0 = sRED + (jpr * 8) + half;
#pragma unroll
                for (int q = 0; q < 8; q++) {
                    const float* pq = rp0 + q * (32 * 8);
                    hr += pq[0];
                    hz += pq[2];
                    hn += pq[4];
                }
                float h_old = sHT[((size_t)(p * 2 + bb) * 256 + j0) * 2];
                float r = sigmoid_ap(xr + hr + bhr);
                float z = sigmoid_ap(xz + hz + bhz);
                float nn = tanh_ap(xn + bin + r * (hn + bhn));
                float h_new = (1.0f - z) * nn + z * h_old;

                ys[((size_t)t * 64 + b_glob) * 256 + j0] = h_new;
                if (t == TT - 1)
                    finalc[(size_t)b_glob * 256 + j0] = h_new;

                if (t + 1 < TT) {
                    unsigned long long hv = dup2(h_new);
                    uint32_t doff = (uint32_t)((n * 2 + bb) * 256 + j0) * 8u;
                    uint32_t moff = (uint32_t)(bb * 2 + n) * 8u;
#pragma unroll
                    for (int r4 = 0; r4 < CSZ; r4++) {
                        st_async_u64(rdata[r4] + doff, hv, rmb[r4] + moff);
                    }
                    // prefetch xi for t+1
                    const float* xp = g_xi + ((size_t)(t + 1) * 64 + b_glob) * 768 + j0;
                    xr = __ldg(xp);
                    xz = __ldg(xp + 256);
                    xn = __ldg(xp + 512);
                }
            }
            __syncthreads();   // sRED consumed before next half overwrites
        }

        // -- end-wait for b0's next h (transit hidden under the b1 half) --
        if (t + 1 < TT) {
            uint32_t mb = mbase + (uint32_t)n * 8u;   // mb[0][n]
            if (n) { mbar_wait_cta(mb, ph01); ph01 ^= 1; }
            else   { mbar_wait_cta(mb, ph00); ph00 ^= 1; }
        }
    }

    // no CTA exits while peers might still write its smem
    asm volatile("barrier.cluster.arrive.aligned;" ::: "memory");
    asm volatile("barrier.cluster.wait.aligned;" ::: "memory");
}

// ============================================================
extern "C" void kernel_launch(void* const* d_in, const int* in_sizes, int n_in,
                              void* d_out, int out_size) {
    const float* c    = (const float*)d_in[0];
    const float* xs   = (const float*)d_in[1];
    const float* Wi   = (const float*)d_in[2];
    const float* Wh   = (const float*)d_in[3];
    const float* bh   = (const float*)d_in[4];
    const float* b_in = (const float*)d_in[5];

    float* dmp;
    cudaGetSymbolAddress((void**)&dmp, g_dump);

    float* out = (float*)d_out;
    float* finalc;
    float* ys;
    const long long full = (long long)BB * HH + (long long)TT * BB * HH;
    if ((long long)out_size >= full) {
        finalc = out;            // tuple order: final_c first, then ys
        ys = out + BB * HH;
    } else if ((long long)out_size >= (long long)TT * BB * HH) {
        ys = out;
        finalc = dmp;
    } else {
        finalc = out;
        ys = dmp;
    }

    // smem attr (mandatory habit after R9/R10)
    cudaFuncSetAttribute(gru_rec_kernel, cudaFuncAttributeMaxDynamicSharedMemorySize, SMEM_BYTES);

    // 1) xi = xs @ Wi (double-buffered, R16-proven)
    dim3 ggrid(NG / 128, (TT * BB) / 128);
    gemm_xi_kernel<<<ggrid, 256>>>(xs, Wi);
    // 2) clustered recurrence (CSZ=4, batch-pipelined)
    gru_rec_kernel<<<NCTA, NT, SMEM_BYTES>>>(c, Wh, bh, b_in, ys, finalc);
}